// round 9
// baseline (speedup 1.0000x reference)
#include <cuda_runtime.h>

#define FULL 0xffffffffu

// ---------------- persistent scratch (self-resetting across graph replays) --
__device__ float    g_F[81 * 8];        // grid evaluations of <Z_j>
__device__ unsigned g_ctr  = 0;         // producers done
__device__ unsigned g_done = 0;         // blocks done
__device__ float    g_partial[32] = {}; // per-batch dense accumulators

// ---------------- warp statevector simulation (producer phase) --------------
struct St { float2 a[8]; };

__device__ __forceinline__ float2 shxor(float2 v, int m) {
    float2 r;
    r.x = __shfl_xor_sync(FULL, v.x, m);
    r.y = __shfl_xor_sync(FULL, v.y, m);
    return r;
}

template<int Q>
__device__ __forceinline__ void gateRY(St& st, float c, float s, int lane) {
    if constexpr (Q >= 5) {
        constexpr int bit = 1 << (7 - Q);
#pragma unroll
        for (int m = 0; m < 8; ++m) {
            if ((m & bit) == 0) {
                float2 a = st.a[m], b = st.a[m | bit];
                st.a[m]       = make_float2(c * a.x - s * b.x, c * a.y - s * b.y);
                st.a[m | bit] = make_float2(s * a.x + c * b.x, s * a.y + c * b.y);
            }
        }
    } else {
        constexpr int lm = 1 << (4 - Q);
        float sg = (lane & lm) ? s : -s;
#pragma unroll
        for (int m = 0; m < 8; ++m) {
            float2 o = shxor(st.a[m], lm);
            float2 a = st.a[m];
            st.a[m] = make_float2(c * a.x + sg * o.x, c * a.y + sg * o.y);
        }
    }
}

template<int Q>
__device__ __forceinline__ void gateRX(St& st, float c, float s, int lane) {
    if constexpr (Q >= 5) {
        constexpr int bit = 1 << (7 - Q);
#pragma unroll
        for (int m = 0; m < 8; ++m) {
            if ((m & bit) == 0) {
                float2 a = st.a[m], b = st.a[m | bit];
                st.a[m]       = make_float2(c * a.x + s * b.y, c * a.y - s * b.x);
                st.a[m | bit] = make_float2(c * b.x + s * a.y, c * b.y - s * a.x);
            }
        }
    } else {
        constexpr int lm = 1 << (4 - Q);
#pragma unroll
        for (int m = 0; m < 8; ++m) {
            float2 o = shxor(st.a[m], lm);
            float2 a = st.a[m];
            st.a[m] = make_float2(c * a.x + s * o.y, c * a.y - s * o.x);
        }
    }
}

template<int Q>
__device__ __forceinline__ void gateRZ(St& st, float c, float s, int lane) {
    if constexpr (Q >= 5) {
        constexpr int bit = 1 << (7 - Q);
#pragma unroll
        for (int m = 0; m < 8; ++m) {
            float f = (m & bit) ? s : -s;
            float2 a = st.a[m];
            st.a[m] = make_float2(c * a.x - f * a.y, c * a.y + f * a.x);
        }
    } else {
        constexpr int lm = 1 << (4 - Q);
        float f = (lane & lm) ? s : -s;
#pragma unroll
        for (int m = 0; m < 8; ++m) {
            float2 a = st.a[m];
            st.a[m] = make_float2(c * a.x - f * a.y, c * a.y + f * a.x);
        }
    }
}

template<int C, int T>
__device__ __forceinline__ void cnot(St& st, int lane) {
    if constexpr (C <= 4 && T <= 4) {
        constexpr int cm = 1 << (4 - C);
        constexpr int tm = 1 << (4 - T);
        bool ctrl = (lane & cm) != 0;
#pragma unroll
        for (int m = 0; m < 8; ++m) {
            float2 o = shxor(st.a[m], tm);
            if (ctrl) st.a[m] = o;
        }
    } else if constexpr (C <= 4 && T >= 5) {
        constexpr int cm = 1 << (4 - C);
        constexpr int tb = 1 << (7 - T);
        bool ctrl = (lane & cm) != 0;
#pragma unroll
        for (int m = 0; m < 8; ++m) {
            if ((m & tb) == 0) {
                float2 a = st.a[m], b = st.a[m | tb];
                st.a[m]      = ctrl ? b : a;
                st.a[m | tb] = ctrl ? a : b;
            }
        }
    } else {
        constexpr int cb = 1 << (7 - C);
        constexpr int tb = 1 << (7 - T);
#pragma unroll
        for (int m = 0; m < 8; ++m) {
            if ((m & cb) != 0 && (m & tb) == 0) {
                float2 t = st.a[m];
                st.a[m] = st.a[m | tb];
                st.a[m | tb] = t;
            }
        }
    }
}

template<int J>
__device__ __forceinline__ void ansatzStep(St& st, const float* cw, const float* sw, int lane) {
    constexpr int C = (J < 7) ? J : 0;
    constexpr int T = (J < 7) ? J + 1 : 7;
    float c = cw[J], s = sw[J];
    gateRX<J>(st, c, s, lane);
    cnot<C, T>(st, lane);
    gateRY<J>(st, c, s, lane);
    cnot<C, T>(st, lane);
    gateRZ<J>(st, c, s, lane);
}

__device__ __forceinline__ void ansatz(St& st, const float* cw, const float* sw, int lane) {
    ansatzStep<0>(st, cw, sw, lane);
    ansatzStep<1>(st, cw, sw, lane);
    ansatzStep<2>(st, cw, sw, lane);
    ansatzStep<3>(st, cw, sw, lane);
    ansatzStep<4>(st, cw, sw, lane);
    ansatzStep<5>(st, cw, sw, lane);
    ansatzStep<6>(st, cw, sw, lane);
    ansatzStep<7>(st, cw, sw, lane);
}

// ---------------- mega kernel: everything in one launch ----------------------
// 256 blocks x 256 threads. bid -> (batch = bid>>3, chunk = bid&7).
// Blocks 0..80: warp 0 additionally produces g_F[bid]. Flag-sync, then every
// block runs transform + layer1 + layer2 + dense partial. Last block to finish
// writes out[] (partial + bias) and resets all persistent state for the next
// graph replay.
#define CH 128
#define NP (CH + 3)    // 131 layer-1 values (halo)
#define NX (CH + 6)    // 134 x-sincos values

__global__ void __launch_bounds__(256) mega_kernel(const float* __restrict__ x,
                                                   const float* __restrict__ weights,
                                                   const float* __restrict__ dw,
                                                   const float* __restrict__ db,
                                                   float* __restrict__ out) {
    __shared__ float cw[24], sw[24];     // producer warp only
    __shared__ float coef[648];          // [ch][81], transformed in place
    __shared__ float xc[NX], xs[NX];     // sincos of input window
    __shared__ float ac[NP], as_[NP];    // sincos of layer-1 relu values
    __shared__ float red[8];

    int t = threadIdx.x;
    int lane = t & 31;
    int wid = t >> 5;
    int bid = blockIdx.x;                // 0..255
    int b  = bid >> 3;                   // batch 0..31
    int s0 = (bid & 7) * CH;             // chunk start

    // ---- x-window sincos (warps 2-6): independent of producers ----
    {
        int k = t - 64;
        if (k >= 0 && k < NX) {
            int l = s0 - 2 + k;
            float cv = 1.f, sv = 0.f;
            if (l >= 0 && l < 1024) __sincosf(x[b * 1024 + l], &sv, &cv);
            xc[k] = cv; xs[k] = sv;
        }
    }

    // ---- producer: blocks 0..80, warp 0 simulates grid circuit n = bid ----
    if (bid < 81 && wid == 0) {
        if (lane < 24) {
            const float TWO_PI = 6.28318530717958647692f;
            float w = weights[lane];
            float wm = fmodf(w, TWO_PI);
            if (wm < 0.f) wm += TWO_PI;
            cw[lane] = cosf(0.5f * wm);
            sw[lane] = sinf(0.5f * wm);
        }
        __syncwarp();

        St st;
#pragma unroll
        for (int m = 0; m < 8; ++m) st.a[m] = make_float2(0.f, 0.f);
        if (lane == 0) st.a[0] = make_float2(1.f, 0.f);
        ansatz(st, &cw[0], &sw[0], lane);

        const float GC[3] = {1.f, 0.70710678118654752440f, 0.f};
        const float GS[3] = {0.f, 0.70710678118654752440f, 1.f};
        int n = bid;
        int k0 = n / 27, k1 = (n / 9) % 3, k2 = (n / 3) % 3, k3 = n % 3;
        gateRY<0>(st, GC[k0], GS[k0], lane);
        gateRY<1>(st, GC[k1], GS[k1], lane);
        gateRY<2>(st, GC[k2], GS[k2], lane);
        gateRY<3>(st, GC[k3], GS[k3], lane);

        ansatz(st, &cw[8],  &sw[8],  lane);
        ansatz(st, &cw[16], &sw[16], lane);

        float vj[8];
#pragma unroll
        for (int j = 0; j < 8; ++j) vj[j] = 0.f;
#pragma unroll
        for (int m = 0; m < 8; ++m) {
            float2 a = st.a[m];
            float p = a.x * a.x + a.y * a.y;
            int idx = (lane << 3) | m;
#pragma unroll
            for (int j = 0; j < 8; ++j) vj[j] += ((idx >> (7 - j)) & 1) ? -p : p;
        }
#pragma unroll
        for (int j = 0; j < 8; ++j) {
#pragma unroll
            for (int o = 16; o; o >>= 1) vj[j] += __shfl_xor_sync(FULL, vj[j], o);
        }
        if (lane == 0) {
#pragma unroll
            for (int j = 0; j < 8; ++j) g_F[n * 8 + j] = vj[j];
            __threadfence();                 // publish g_F before counting
            atomicAdd(&g_ctr, 1u);
        }
    }

    // ---- flag-sync: producers are all in wave 1, so this cannot deadlock ----
    if (t == 255) {
        while (atomicAdd(&g_ctr, 0u) < 81u) __nanosleep(64);
        __threadfence();
    }
    __syncthreads();

    // ---- load F transposed: coef[j*81+n] = g_F[n*8+j] ----
    for (int i = t; i < 648; i += 256) {
        int j = i / 81, n = i - j * 81;
        coef[i] = g_F[n * 8 + j];
    }
    __syncthreads();

    // ---- transform: per-axis {1,cos,sin} extraction, in place (4 passes) ----
#pragma unroll
    for (int a = 0; a < 4; ++a) {
        const int stv = (a == 0) ? 27 : (a == 1) ? 9 : (a == 2) ? 3 : 1;
        if (t < 216) {
            int j = t / 27, r = t - j * 27;
            int base = j * 81 + (r / stv) * (3 * stv) + (r % stv);
            float f0 = coef[base], f1 = coef[base + stv], f2 = coef[base + 2 * stv];
            float kc = 0.5f * (f0 + f2);
            coef[base]           = kc;
            coef[base + stv]     = 0.5f * (f0 - f2);
            coef[base + 2 * stv] = f1 - kc;
        }
        __syncthreads();
    }

    // ---- layer 1: thread-per-position (p = s0 - 1 + t), t < NP ----
    if (t < NP) {
        int p = s0 - 1 + t;
        float cv = 1.f, sv = 0.f;            // OOB position -> angle 0
        if (p >= 0 && p < 1023) {
            float t0c = xc[t],     t0s = xs[t];
            float t1c = xc[t + 1], t1s = xs[t + 1];
            float t23[9];
            {
                float t2[3] = {1.f, xc[t + 2], xs[t + 2]};
                float t3[3] = {1.f, xc[t + 3], xs[t + 3]};
#pragma unroll
                for (int i = 0; i < 3; ++i)
#pragma unroll
                    for (int j = 0; j < 3; ++j) t23[i * 3 + j] = t2[i] * t3[j];
            }
            float v = 0.f;
#pragma unroll
            for (int i = 0; i < 9; ++i) {
                float pp = 0.f;
#pragma unroll
                for (int l = 0; l < 9; ++l) pp = fmaf(coef[i * 9 + l], t23[l], pp);
                float f0 = (i < 3) ? 1.f : (i < 6) ? t0c : t0s;
                float f1 = (i % 3 == 0) ? 1.f : (i % 3 == 1) ? t1c : t1s;
                v = fmaf(f0 * f1, pp, v);
            }
            __sincosf(fmaxf(v, 0.f), &sv, &cv);
        }
        ac[t] = cv; as_[t] = sv;
    }
    __syncthreads();

    // ---- layer 2: thread = (channel = t&7, 4 positions 4q..4q+3) ----
    int ch = t & 7;
    int q  = t >> 3;
    int p0 = 4 * q;

    float t23[4][9];
    float c0[4], s0v[4], c1[4], s1v[4];
#pragma unroll
    for (int r = 0; r < 4; ++r) {
        int p = p0 + r;
        c0[r] = ac[p];     s0v[r] = as_[p];
        c1[r] = ac[p + 1]; s1v[r] = as_[p + 1];
        float t2[3] = {1.f, ac[p + 2], as_[p + 2]};
        float t3[3] = {1.f, ac[p + 3], as_[p + 3]};
#pragma unroll
        for (int i = 0; i < 3; ++i)
#pragma unroll
            for (int j = 0; j < 3; ++j) t23[r][i * 3 + j] = t2[i] * t3[j];
    }

    const float* sc = &coef[ch * 81];
    float acc[4] = {0.f, 0.f, 0.f, 0.f};
#pragma unroll
    for (int i = 0; i < 9; ++i) {
        float row[9];
#pragma unroll
        for (int l = 0; l < 9; ++l) row[l] = sc[i * 9 + l];
#pragma unroll
        for (int r = 0; r < 4; ++r) {
            float d = 0.f;
#pragma unroll
            for (int l = 0; l < 9; ++l) d = fmaf(row[l], t23[r][l], d);
            float f0 = (i < 3) ? 1.f : (i < 6) ? c0[r] : s0v[r];
            float f1 = (i % 3 == 0) ? 1.f : (i % 3 == 1) ? c1[r] : s1v[r];
            acc[r] = fmaf(f0 * f1, d, acc[r]);
        }
    }

    // channel max across octet (warp-uniform shuffles)
#pragma unroll
    for (int r = 0; r < 4; ++r) {
        acc[r] = fmaxf(acc[r], __shfl_xor_sync(FULL, acc[r], 1));
        acc[r] = fmaxf(acc[r], __shfl_xor_sync(FULL, acc[r], 2));
        acc[r] = fmaxf(acc[r], __shfl_xor_sync(FULL, acc[r], 4));
    }

    // dense contributions (relu(max) == max(relu))
    float contrib = 0.f;
    if (ch == 0) {
#pragma unroll
        for (int r = 0; r < 4; ++r) {
            int s = s0 + p0 + r;
            if (s < 1022) contrib += fmaxf(acc[r], 0.f) * dw[s];
        }
    }
    contrib += __shfl_xor_sync(FULL, contrib, 8);
    contrib += __shfl_xor_sync(FULL, contrib, 16);
    if (lane == 0) red[wid] = contrib;
    __syncthreads();

    // ---- block total -> global partial; last block finalizes + resets ----
    if (t == 0) {
        float r = 0.f;
#pragma unroll
        for (int w = 0; w < 8; ++w) r += red[w];
        atomicAdd(&g_partial[b], r);
        __threadfence();                        // partial visible before done++
        unsigned old = atomicAdd(&g_done, 1u);
        if (old == 255u) {                      // last block of this replay
            __threadfence();
            float bias = db[0];
#pragma unroll 4
            for (int bb = 0; bb < 32; ++bb) {
                float p = atomicAdd(&g_partial[bb], 0.f);   // coherent read
                out[bb] = p + bias;
                atomicExch(&g_partial[bb], 0.f);            // reset for next replay
            }
            atomicExch(&g_ctr, 0u);
            atomicExch(&g_done, 0u);
            __threadfence();
        }
    }
}

// ---------------- launch ------------------------------------------------------
extern "C" void kernel_launch(void* const* d_in, const int* in_sizes, int n_in,
                              void* d_out, int out_size) {
    const float* x       = (const float*)d_in[0];   // (32,1024,1)
    const float* weights = (const float*)d_in[1];   // (3,8)
    const float* dw      = (const float*)d_in[2];   // (1022,1)
    const float* db      = (const float*)d_in[3];   // (1,)
    float* out = (float*)d_out;                     // (32,1)

    mega_kernel<<<256, 256>>>(x, weights, dw, db, out);
}

// round 10
// speedup vs baseline: 2.1070x; 2.1070x over previous
#include <cuda_runtime.h>

#define FULL 0xffffffffu

// ---------------- scratch ----------------------------------------------------
__device__ float g_F[81 * 8];     // grid evaluations of <Z_j>, layout [n][j]

// ---------------- warp statevector simulation (gridsim only) ----------------
// flat index i = lane*8 + m. qubit q (0..4) -> lane bit (4-q); qubit q (5..7)
// -> m bit (7-q).
struct St { float2 a[8]; };

__device__ __forceinline__ float2 shxor(float2 v, int m) {
    float2 r;
    r.x = __shfl_xor_sync(FULL, v.x, m);
    r.y = __shfl_xor_sync(FULL, v.y, m);
    return r;
}

// RY (used for data encoding on qubits 0-3: lane-bit qubits)
template<int Q>
__device__ __forceinline__ void gateRY(St& st, float c, float s, int lane) {
    constexpr int lm = 1 << (4 - Q);
    float sg = (lane & lm) ? s : -s;
#pragma unroll
    for (int m = 0; m < 8; ++m) {
        float2 o = shxor(st.a[m], lm);
        float2 a = st.a[m];
        st.a[m] = make_float2(c * a.x + sg * o.x, c * a.y + sg * o.y);
    }
}

// RX = [[c,-is],[-is,c]] : new = c*own - i*s*other
template<int Q>
__device__ __forceinline__ void gateRX(St& st, float c, float s, int lane) {
    if constexpr (Q >= 5) {
        constexpr int bit = 1 << (7 - Q);
#pragma unroll
        for (int m = 0; m < 8; ++m) {
            if ((m & bit) == 0) {
                float2 a = st.a[m], b = st.a[m | bit];
                st.a[m]       = make_float2(c * a.x + s * b.y, c * a.y - s * b.x);
                st.a[m | bit] = make_float2(c * b.x + s * a.y, c * b.y - s * a.x);
            }
        }
    } else {
        constexpr int lm = 1 << (4 - Q);
#pragma unroll
        for (int m = 0; m < 8; ++m) {
            float2 o = shxor(st.a[m], lm);
            float2 a = st.a[m];
            st.a[m] = make_float2(c * a.x + s * o.y, c * a.y - s * o.x);
        }
    }
}

// RZ = diag(e^{-it/2}, e^{+it/2})
template<int Q>
__device__ __forceinline__ void gateRZ(St& st, float c, float s, int lane) {
    if constexpr (Q >= 5) {
        constexpr int bit = 1 << (7 - Q);
#pragma unroll
        for (int m = 0; m < 8; ++m) {
            float f = (m & bit) ? s : -s;
            float2 a = st.a[m];
            st.a[m] = make_float2(c * a.x - f * a.y, c * a.y + f * a.x);
        }
    } else {
        constexpr int lm = 1 << (4 - Q);
        float f = (lane & lm) ? s : -s;
#pragma unroll
        for (int m = 0; m < 8; ++m) {
            float2 a = st.a[m];
            st.a[m] = make_float2(c * a.x - f * a.y, c * a.y + f * a.x);
        }
    }
}

// Fused CNOT·RY·CNOT:
//  j<7 (rotation on control c=j, target t=j+1): exp(-i t/2 Y_c X_t)
//    new[i] = c*a[i] + (b_c(i) ? +s : -s) * a[i flip(c,t)]
//  j=7 (c=0, t=7; rotation on target): exp(-i t/2 Z_c Y_t)
//    new[i] = c*a[i] + ((b_c^b_t) ? +s : -s) * a[i flip(t)]
template<int J>
__device__ __forceinline__ void fusedW(St& st, float c, float s, int lane) {
    if constexpr (J <= 3) {
        // both qubits in lane bits: single shfl_xor butterfly
        constexpr int cm = 1 << (4 - J);
        constexpr int tm = 1 << (3 - J);
        float sg = (lane & cm) ? s : -s;
#pragma unroll
        for (int m = 0; m < 8; ++m) {
            float2 o = shxor(st.a[m], cm | tm);
            float2 a = st.a[m];
            st.a[m] = make_float2(c * a.x + sg * o.x, c * a.y + sg * o.y);
        }
    } else if constexpr (J == 4) {
        // c = qubit 4 (lane bit 0), t = qubit 5 (m bit 2)
        float sg = (lane & 1) ? s : -s;
        float2 o[8];
#pragma unroll
        for (int m = 0; m < 8; ++m) o[m] = shxor(st.a[m ^ 4], 1);
#pragma unroll
        for (int m = 0; m < 8; ++m) {
            float2 a = st.a[m];
            st.a[m] = make_float2(c * a.x + sg * o[m].x, c * a.y + sg * o[m].y);
        }
    } else if constexpr (J == 5 || J == 6) {
        // both qubits local: c mask, t mask in m bits
        constexpr int cmask = (J == 5) ? 4 : 2;
        constexpr int xmask = (J == 5) ? 6 : 3;   // cmask | tmask
        float2 old[8];
#pragma unroll
        for (int m = 0; m < 8; ++m) old[m] = st.a[m];
#pragma unroll
        for (int m = 0; m < 8; ++m) {
            float sg = (m & cmask) ? s : -s;
            st.a[m] = make_float2(c * old[m].x + sg * old[m ^ xmask].x,
                                  c * old[m].y + sg * old[m ^ xmask].y);
        }
    } else {
        // J == 7: c = qubit 0 (lane bit 4), t = qubit 7 (m bit 0); local butterfly
        int bc = (lane >> 4) & 1;
        float2 old[8];
#pragma unroll
        for (int m = 0; m < 8; ++m) old[m] = st.a[m];
#pragma unroll
        for (int m = 0; m < 8; ++m) {
            float sg = ((bc ^ (m & 1)) != 0) ? s : -s;
            st.a[m] = make_float2(c * old[m].x + sg * old[m ^ 1].x,
                                  c * old[m].y + sg * old[m ^ 1].y);
        }
    }
}

template<int J>
__device__ __forceinline__ void ansatzStep(St& st, const float* cw, const float* sw, int lane) {
    float c = cw[J], s = sw[J];
    gateRX<J>(st, c, s, lane);
    fusedW<J>(st, c, s, lane);
    gateRZ<J>(st, c, s, lane);
}

__device__ __forceinline__ void ansatz(St& st, const float* cw, const float* sw, int lane) {
    ansatzStep<0>(st, cw, sw, lane);
    ansatzStep<1>(st, cw, sw, lane);
    ansatzStep<2>(st, cw, sw, lane);
    ansatzStep<3>(st, cw, sw, lane);
    ansatzStep<4>(st, cw, sw, lane);
    ansatzStep<5>(st, cw, sw, lane);
    ansatzStep<6>(st, cw, sw, lane);
    ansatzStep<7>(st, cw, sw, lane);
}

// ---------------- kernel 1: 81 grid circuits (each block self-contained) ----
__global__ void gridsim_kernel(const float* __restrict__ weights,
                               const float* __restrict__ db,
                               float* __restrict__ out) {
    __shared__ float cw[24], sw[24];
    int lane = threadIdx.x;

    if (blockIdx.x == 0) out[lane] = db[0];   // seed output with bias

    if (lane < 24) {
        const float TWO_PI = 6.28318530717958647692f;
        float w = weights[lane];
        float wm = fmodf(w, TWO_PI);
        if (wm < 0.f) wm += TWO_PI;
        cw[lane] = cosf(0.5f * wm);
        sw[lane] = sinf(0.5f * wm);
    }
    __syncwarp();

    St st;
#pragma unroll
    for (int m = 0; m < 8; ++m) st.a[m] = make_float2(0.f, 0.f);
    if (lane == 0) st.a[0] = make_float2(1.f, 0.f);
    ansatz(st, &cw[0], &sw[0], lane);

    const float GC[3] = {1.f, 0.70710678118654752440f, 0.f};
    const float GS[3] = {0.f, 0.70710678118654752440f, 1.f};
    int n = blockIdx.x;
    int k0 = n / 27, k1 = (n / 9) % 3, k2 = (n / 3) % 3, k3 = n % 3;
    gateRY<0>(st, GC[k0], GS[k0], lane);
    gateRY<1>(st, GC[k1], GS[k1], lane);
    gateRY<2>(st, GC[k2], GS[k2], lane);
    gateRY<3>(st, GC[k3], GS[k3], lane);

    ansatz(st, &cw[8],  &sw[8],  lane);
    ansatz(st, &cw[16], &sw[16], lane);

    float vj[8];
#pragma unroll
    for (int j = 0; j < 8; ++j) vj[j] = 0.f;
#pragma unroll
    for (int m = 0; m < 8; ++m) {
        float2 a = st.a[m];
        float p = a.x * a.x + a.y * a.y;
        int idx = (lane << 3) | m;
#pragma unroll
        for (int j = 0; j < 8; ++j) vj[j] += ((idx >> (7 - j)) & 1) ? -p : p;
    }
#pragma unroll
    for (int j = 0; j < 8; ++j) {
#pragma unroll
        for (int o = 16; o; o >>= 1) vj[j] += __shfl_xor_sync(FULL, vj[j], o);
    }
    if (lane == 0) {
#pragma unroll
        for (int j = 0; j < 8; ++j) g_F[n * 8 + j] = vj[j];
    }
}

// ---------------- kernel 2: transform + layer1 + layer2 + pool + dense ------
// 256 threads; thread = (channel = t&7, 4 positions 4q..4q+3, q = t>>3)
// block covers CH = 128 layer-2 positions; grid (8, 32)
#define CH 128
#define NP (CH + 3)    // 131 layer-1 values (halo)
#define NX (CH + 6)    // 134 x-sincos values

__global__ void __launch_bounds__(256) fused_kernel(const float* __restrict__ x,
                                                    const float* __restrict__ dw,
                                                    float* __restrict__ out) {
    __shared__ float coef[648];          // [ch][81], transformed in place
    __shared__ float xc[NX], xs[NX];     // sincos of input window
    __shared__ float ac[NP], as_[NP];    // sincos of layer-1 relu values
    __shared__ float red[8];

    int t = threadIdx.x;
    int lane = t & 31;
    int warp = t >> 5;
    int b = blockIdx.y;
    int s0 = blockIdx.x * CH;

    // --- load F transposed: coef[j*81+n] = g_F[n*8+j] ---
    for (int i = t; i < 648; i += 256) {
        int j = i / 81, n = i - j * 81;
        coef[i] = g_F[n * 8 + j];
    }
    // --- sincos of x window: x index l = s0-2+k ---
    if (t < NX) {
        int l = s0 - 2 + t;
        float cv = 1.f, sv = 0.f;
        if (l >= 0 && l < 1024) __sincosf(x[b * 1024 + l], &sv, &cv);
        xc[t] = cv; xs[t] = sv;
    }
    __syncthreads();

    // --- transform: per-axis {1,cos,sin} extraction, in place (4 passes) ---
#pragma unroll
    for (int a = 0; a < 4; ++a) {
        const int stv = (a == 0) ? 27 : (a == 1) ? 9 : (a == 2) ? 3 : 1;
        if (t < 216) {
            int j = t / 27, r = t - j * 27;
            int base = j * 81 + (r / stv) * (3 * stv) + (r % stv);
            float f0 = coef[base], f1 = coef[base + stv], f2 = coef[base + 2 * stv];
            float kc = 0.5f * (f0 + f2);
            coef[base]           = kc;
            coef[base + stv]     = 0.5f * (f0 - f2);
            coef[base + 2 * stv] = f1 - kc;
        }
        __syncthreads();
    }

    // --- layer 1: thread-per-position (p = s0 - 1 + t), t < NP=131 ---
    if (t < NP) {
        int p = s0 - 1 + t;
        float cv = 1.f, sv = 0.f;          // OOB position -> angle 0
        if (p >= 0 && p < 1023) {
            float t0c = xc[t],     t0s = xs[t];
            float t1c = xc[t + 1], t1s = xs[t + 1];
            float t23[9];
            {
                float t2[3] = {1.f, xc[t + 2], xs[t + 2]};
                float t3[3] = {1.f, xc[t + 3], xs[t + 3]};
#pragma unroll
                for (int i = 0; i < 3; ++i)
#pragma unroll
                    for (int j = 0; j < 3; ++j) t23[i * 3 + j] = t2[i] * t3[j];
            }
            float v = 0.f;
#pragma unroll
            for (int i = 0; i < 9; ++i) {
                float pp = 0.f;
#pragma unroll
                for (int l = 0; l < 9; ++l) pp = fmaf(coef[i * 9 + l], t23[l], pp);
                float f0 = (i < 3) ? 1.f : (i < 6) ? t0c : t0s;
                float f1 = (i % 3 == 0) ? 1.f : (i % 3 == 1) ? t1c : t1s;
                v = fmaf(f0 * f1, pp, v);
            }
            __sincosf(fmaxf(v, 0.f), &sv, &cv);
        }
        ac[t] = cv; as_[t] = sv;
    }
    __syncthreads();

    // --- layer 2: thread = (channel, 4 positions); sc row LDS feeds 4 chains
    int ch = t & 7;
    int q  = t >> 3;                     // 0..31 -> local positions 4q..4q+3
    int p0 = 4 * q;

    float t23[4][9];
    float c0[4], s0v[4], c1[4], s1v[4];
#pragma unroll
    for (int r = 0; r < 4; ++r) {
        int p = p0 + r;
        c0[r] = ac[p];     s0v[r] = as_[p];
        c1[r] = ac[p + 1]; s1v[r] = as_[p + 1];
        float t2[3] = {1.f, ac[p + 2], as_[p + 2]};
        float t3[3] = {1.f, ac[p + 3], as_[p + 3]};
#pragma unroll
        for (int i = 0; i < 3; ++i)
#pragma unroll
            for (int j = 0; j < 3; ++j) t23[r][i * 3 + j] = t2[i] * t3[j];
    }

    const float* sc = &coef[ch * 81];
    float acc[4] = {0.f, 0.f, 0.f, 0.f};
#pragma unroll
    for (int i = 0; i < 9; ++i) {
        float row[9];
#pragma unroll
        for (int l = 0; l < 9; ++l) row[l] = sc[i * 9 + l];
#pragma unroll
        for (int r = 0; r < 4; ++r) {
            float d = 0.f;
#pragma unroll
            for (int l = 0; l < 9; ++l) d = fmaf(row[l], t23[r][l], d);
            float f0 = (i < 3) ? 1.f : (i < 6) ? c0[r] : s0v[r];
            float f1 = (i % 3 == 0) ? 1.f : (i % 3 == 1) ? c1[r] : s1v[r];
            acc[r] = fmaf(f0 * f1, d, acc[r]);
        }
    }

    // channel max across octet (warp-uniform shuffles)
#pragma unroll
    for (int r = 0; r < 4; ++r) {
        acc[r] = fmaxf(acc[r], __shfl_xor_sync(FULL, acc[r], 1));
        acc[r] = fmaxf(acc[r], __shfl_xor_sync(FULL, acc[r], 2));
        acc[r] = fmaxf(acc[r], __shfl_xor_sync(FULL, acc[r], 4));
    }

    // dense contributions (relu(max) == max(relu))
    float contrib = 0.f;
    if (ch == 0) {
#pragma unroll
        for (int r = 0; r < 4; ++r) {
            int s = s0 + p0 + r;
            if (s < 1022) contrib += fmaxf(acc[r], 0.f) * dw[s];
        }
    }
    contrib += __shfl_xor_sync(FULL, contrib, 8);
    contrib += __shfl_xor_sync(FULL, contrib, 16);
    if (lane == 0) red[warp] = contrib;
    __syncthreads();
    if (warp == 0) {
        float r = (lane < 8) ? red[lane] : 0.f;
        r += __shfl_xor_sync(FULL, r, 1);
        r += __shfl_xor_sync(FULL, r, 2);
        r += __shfl_xor_sync(FULL, r, 4);
        if (lane == 0) atomicAdd(&out[b], r);
    }
}

// ---------------- launch ------------------------------------------------------
extern "C" void kernel_launch(void* const* d_in, const int* in_sizes, int n_in,
                              void* d_out, int out_size) {
    const float* x       = (const float*)d_in[0];   // (32,1024,1)
    const float* weights = (const float*)d_in[1];   // (3,8)
    const float* dw      = (const float*)d_in[2];   // (1022,1)
    const float* db      = (const float*)d_in[3];   // (1,)
    float* out = (float*)d_out;                     // (32,1)

    gridsim_kernel<<<81, 32>>>(weights, db, out);
    dim3 g((1022 + CH - 1) / CH, 32);               // (8, 32)
    fused_kernel<<<g, 256>>>(x, dw, out);
}

// round 11
// speedup vs baseline: 2.1209x; 1.0066x over previous
#include <cuda_runtime.h>

#define FULL 0xffffffffu

// ---------------- scratch ----------------------------------------------------
__device__ float g_F[8 * 81];     // grid evaluations of <Z_j>, layout [j][n]

// ---------------- warp statevector simulation (gridsim only) ----------------
// flat index i = lane*8 + m. qubit q (0..4) -> lane bit (4-q); qubit q (5..7)
// -> m bit (7-q).
struct St { float2 a[8]; };

__device__ __forceinline__ float2 shxor(float2 v, int m) {
    float2 r;
    r.x = __shfl_xor_sync(FULL, v.x, m);
    r.y = __shfl_xor_sync(FULL, v.y, m);
    return r;
}

// RY (data encoding on qubits 0-3: lane-bit qubits)
template<int Q>
__device__ __forceinline__ void gateRY(St& st, float c, float s, int lane) {
    constexpr int lm = 1 << (4 - Q);
    float sg = (lane & lm) ? s : -s;
#pragma unroll
    for (int m = 0; m < 8; ++m) {
        float2 o = shxor(st.a[m], lm);
        float2 a = st.a[m];
        st.a[m] = make_float2(c * a.x + sg * o.x, c * a.y + sg * o.y);
    }
}

// RX = [[c,-is],[-is,c]]
template<int Q>
__device__ __forceinline__ void gateRX(St& st, float c, float s, int lane) {
    if constexpr (Q >= 5) {
        constexpr int bit = 1 << (7 - Q);
#pragma unroll
        for (int m = 0; m < 8; ++m) {
            if ((m & bit) == 0) {
                float2 a = st.a[m], b = st.a[m | bit];
                st.a[m]       = make_float2(c * a.x + s * b.y, c * a.y - s * b.x);
                st.a[m | bit] = make_float2(c * b.x + s * a.y, c * b.y - s * a.x);
            }
        }
    } else {
        constexpr int lm = 1 << (4 - Q);
#pragma unroll
        for (int m = 0; m < 8; ++m) {
            float2 o = shxor(st.a[m], lm);
            float2 a = st.a[m];
            st.a[m] = make_float2(c * a.x + s * o.y, c * a.y - s * o.x);
        }
    }
}

// RZ = diag(e^{-it/2}, e^{+it/2})
template<int Q>
__device__ __forceinline__ void gateRZ(St& st, float c, float s, int lane) {
    if constexpr (Q >= 5) {
        constexpr int bit = 1 << (7 - Q);
#pragma unroll
        for (int m = 0; m < 8; ++m) {
            float f = (m & bit) ? s : -s;
            float2 a = st.a[m];
            st.a[m] = make_float2(c * a.x - f * a.y, c * a.y + f * a.x);
        }
    } else {
        constexpr int lm = 1 << (4 - Q);
        float f = (lane & lm) ? s : -s;
#pragma unroll
        for (int m = 0; m < 8; ++m) {
            float2 a = st.a[m];
            st.a[m] = make_float2(c * a.x - f * a.y, c * a.y + f * a.x);
        }
    }
}

// Fused CNOT·RY·CNOT (see round-10 derivation)
template<int J>
__device__ __forceinline__ void fusedW(St& st, float c, float s, int lane) {
    if constexpr (J <= 3) {
        constexpr int cm = 1 << (4 - J);
        constexpr int tm = 1 << (3 - J);
        float sg = (lane & cm) ? s : -s;
#pragma unroll
        for (int m = 0; m < 8; ++m) {
            float2 o = shxor(st.a[m], cm | tm);
            float2 a = st.a[m];
            st.a[m] = make_float2(c * a.x + sg * o.x, c * a.y + sg * o.y);
        }
    } else if constexpr (J == 4) {
        float sg = (lane & 1) ? s : -s;
        float2 o[8];
#pragma unroll
        for (int m = 0; m < 8; ++m) o[m] = shxor(st.a[m ^ 4], 1);
#pragma unroll
        for (int m = 0; m < 8; ++m) {
            float2 a = st.a[m];
            st.a[m] = make_float2(c * a.x + sg * o[m].x, c * a.y + sg * o[m].y);
        }
    } else if constexpr (J == 5 || J == 6) {
        constexpr int cmask = (J == 5) ? 4 : 2;
        constexpr int xmask = (J == 5) ? 6 : 3;
        float2 old[8];
#pragma unroll
        for (int m = 0; m < 8; ++m) old[m] = st.a[m];
#pragma unroll
        for (int m = 0; m < 8; ++m) {
            float sg = (m & cmask) ? s : -s;
            st.a[m] = make_float2(c * old[m].x + sg * old[m ^ xmask].x,
                                  c * old[m].y + sg * old[m ^ xmask].y);
        }
    } else {
        int bc = (lane >> 4) & 1;
        float2 old[8];
#pragma unroll
        for (int m = 0; m < 8; ++m) old[m] = st.a[m];
#pragma unroll
        for (int m = 0; m < 8; ++m) {
            float sg = ((bc ^ (m & 1)) != 0) ? s : -s;
            st.a[m] = make_float2(c * old[m].x + sg * old[m ^ 1].x,
                                  c * old[m].y + sg * old[m ^ 1].y);
        }
    }
}

template<int J>
__device__ __forceinline__ void ansatzStep(St& st, const float* cw, const float* sw, int lane) {
    float c = cw[J], s = sw[J];
    gateRX<J>(st, c, s, lane);
    fusedW<J>(st, c, s, lane);
    gateRZ<J>(st, c, s, lane);
}

__device__ __forceinline__ void ansatz(St& st, const float* cw, const float* sw, int lane) {
    ansatzStep<0>(st, cw, sw, lane);
    ansatzStep<1>(st, cw, sw, lane);
    ansatzStep<2>(st, cw, sw, lane);
    ansatzStep<3>(st, cw, sw, lane);
    ansatzStep<4>(st, cw, sw, lane);
    ansatzStep<5>(st, cw, sw, lane);
    ansatzStep<6>(st, cw, sw, lane);
    ansatzStep<7>(st, cw, sw, lane);
}

// ---------------- kernel 1: 81 grid circuits (each block self-contained) ----
__global__ void gridsim_kernel(const float* __restrict__ weights,
                               const float* __restrict__ db,
                               float* __restrict__ out) {
    __shared__ float cw[24], sw[24];
    int lane = threadIdx.x;

    if (blockIdx.x == 0) out[lane] = db[0];   // seed output with bias

    if (lane < 24) {
        const float TWO_PI = 6.28318530717958647692f;
        float w = weights[lane];
        float wm = fmodf(w, TWO_PI);
        if (wm < 0.f) wm += TWO_PI;
        float sv, cv;
        __sincosf(0.5f * wm, &sv, &cv);   // wm/2 in [0,pi): fast path accurate
        cw[lane] = cv;
        sw[lane] = sv;
    }
    __syncwarp();

    St st;
#pragma unroll
    for (int m = 0; m < 8; ++m) st.a[m] = make_float2(0.f, 0.f);
    if (lane == 0) st.a[0] = make_float2(1.f, 0.f);
    ansatz(st, &cw[0], &sw[0], lane);

    const float GC[3] = {1.f, 0.70710678118654752440f, 0.f};
    const float GS[3] = {0.f, 0.70710678118654752440f, 1.f};
    int n = blockIdx.x;
    int k0 = n / 27, k1 = (n / 9) % 3, k2 = (n / 3) % 3, k3 = n % 3;
    gateRY<0>(st, GC[k0], GS[k0], lane);
    gateRY<1>(st, GC[k1], GS[k1], lane);
    gateRY<2>(st, GC[k2], GS[k2], lane);
    gateRY<3>(st, GC[k3], GS[k3], lane);

    ansatz(st, &cw[8],  &sw[8],  lane);
    ansatz(st, &cw[16], &sw[16], lane);

    float vj[8];
#pragma unroll
    for (int j = 0; j < 8; ++j) vj[j] = 0.f;
#pragma unroll
    for (int m = 0; m < 8; ++m) {
        float2 a = st.a[m];
        float p = a.x * a.x + a.y * a.y;
        int idx = (lane << 3) | m;
#pragma unroll
        for (int j = 0; j < 8; ++j) vj[j] += ((idx >> (7 - j)) & 1) ? -p : p;
    }
#pragma unroll
    for (int j = 0; j < 8; ++j) {
#pragma unroll
        for (int o = 16; o; o >>= 1) vj[j] += __shfl_xor_sync(FULL, vj[j], o);
    }
    if (lane == 0) {
#pragma unroll
        for (int j = 0; j < 8; ++j) g_F[j * 81 + n] = vj[j];   // transposed
    }
}

// ---------------- kernel 2: layer1 + layer2 + pool + dense (dual basis) -----
// Evaluation uses Lagrange-trig basis L0=(1+c-s)/2, L1=s, L2=(1-c-s)/2 per
// axis, so the RAW grid values g_F are the coefficients — no transform pass.
// 256 threads; thread = (channel = t&7, 4 positions 4q..4q+3, q = t>>3)
// block covers CH = 128 layer-2 positions; grid (8, 32)
#define CH 128
#define NP (CH + 3)    // 131 layer-1 values (halo)
#define NX (CH + 6)    // 134 x-sincos values

// per-axis dual basis from (cos a, sin a)
__device__ __forceinline__ void lag3(float cv, float sv, float* e) {
    e[0] = 0.5f * (1.f + cv - sv);
    e[1] = sv;
    e[2] = 0.5f * (1.f - cv - sv);
}

__global__ void __launch_bounds__(256) fused_kernel(const float* __restrict__ x,
                                                    const float* __restrict__ dw,
                                                    float* __restrict__ out) {
    __shared__ float coef[648];          // [ch][81] raw grid values
    __shared__ float xc[NX], xs[NX];     // sincos of input window
    __shared__ float ac[NP], as_[NP];    // sincos of layer-1 relu values
    __shared__ float red[8];

    int t = threadIdx.x;
    int lane = t & 31;
    int warp = t >> 5;
    int b = blockIdx.y;
    int s0 = blockIdx.x * CH;

    // --- straight copy (g_F already [j][81]) ---
    for (int i = t; i < 648; i += 256) coef[i] = g_F[i];
    // --- sincos of x window: x index l = s0-2+k ---
    if (t < NX) {
        int l = s0 - 2 + t;
        float cv = 1.f, sv = 0.f;
        if (l >= 0 && l < 1024) __sincosf(x[b * 1024 + l], &sv, &cv);
        xc[t] = cv; xs[t] = sv;
    }
    __syncthreads();

    // --- layer 1: thread-per-position (p = s0 - 1 + t), t < NP=131 ---
    if (t < NP) {
        int p = s0 - 1 + t;
        float cv = 1.f, sv = 0.f;          // OOB position -> angle 0
        if (p >= 0 && p < 1023) {
            float e0[3], e1[3], t23[9];
            lag3(xc[t], xs[t], e0);
            lag3(xc[t + 1], xs[t + 1], e1);
            {
                float e2[3], e3[3];
                lag3(xc[t + 2], xs[t + 2], e2);
                lag3(xc[t + 3], xs[t + 3], e3);
#pragma unroll
                for (int i = 0; i < 3; ++i)
#pragma unroll
                    for (int j = 0; j < 3; ++j) t23[i * 3 + j] = e2[i] * e3[j];
            }
            float v = 0.f;
#pragma unroll
            for (int i = 0; i < 9; ++i) {
                float pp = 0.f;
#pragma unroll
                for (int l = 0; l < 9; ++l) pp = fmaf(coef[i * 9 + l], t23[l], pp);
                v = fmaf(e0[i / 3] * e1[i % 3], pp, v);
            }
            __sincosf(fmaxf(v, 0.f), &sv, &cv);
        }
        ac[t] = cv; as_[t] = sv;
    }
    __syncthreads();

    // --- layer 2: thread = (channel, 4 positions); coef row LDS feeds 4 chains
    int ch = t & 7;
    int q  = t >> 3;                     // 0..31 -> local positions 4q..4q+3
    int p0 = 4 * q;

    float t23[4][9];
    float e0r[4][3], e1r[4][3];
#pragma unroll
    for (int r = 0; r < 4; ++r) {
        int p = p0 + r;
        lag3(ac[p],     as_[p],     e0r[r]);
        lag3(ac[p + 1], as_[p + 1], e1r[r]);
        float e2[3], e3[3];
        lag3(ac[p + 2], as_[p + 2], e2);
        lag3(ac[p + 3], as_[p + 3], e3);
#pragma unroll
        for (int i = 0; i < 3; ++i)
#pragma unroll
            for (int j = 0; j < 3; ++j) t23[r][i * 3 + j] = e2[i] * e3[j];
    }

    const float* sc = &coef[ch * 81];
    float acc[4] = {0.f, 0.f, 0.f, 0.f};
#pragma unroll
    for (int i = 0; i < 9; ++i) {
        float row[9];
#pragma unroll
        for (int l = 0; l < 9; ++l) row[l] = sc[i * 9 + l];
#pragma unroll
        for (int r = 0; r < 4; ++r) {
            float d = 0.f;
#pragma unroll
            for (int l = 0; l < 9; ++l) d = fmaf(row[l], t23[r][l], d);
            acc[r] = fmaf(e0r[r][i / 3] * e1r[r][i % 3], d, acc[r]);
        }
    }

    // channel max across octet (warp-uniform shuffles)
#pragma unroll
    for (int r = 0; r < 4; ++r) {
        acc[r] = fmaxf(acc[r], __shfl_xor_sync(FULL, acc[r], 1));
        acc[r] = fmaxf(acc[r], __shfl_xor_sync(FULL, acc[r], 2));
        acc[r] = fmaxf(acc[r], __shfl_xor_sync(FULL, acc[r], 4));
    }

    // dense contributions (relu(max) == max(relu))
    float contrib = 0.f;
    if (ch == 0) {
#pragma unroll
        for (int r = 0; r < 4; ++r) {
            int s = s0 + p0 + r;
            if (s < 1022) contrib += fmaxf(acc[r], 0.f) * dw[s];
        }
    }
    contrib += __shfl_xor_sync(FULL, contrib, 8);
    contrib += __shfl_xor_sync(FULL, contrib, 16);
    if (lane == 0) red[warp] = contrib;
    __syncthreads();
    if (warp == 0) {
        float r = (lane < 8) ? red[lane] : 0.f;
        r += __shfl_xor_sync(FULL, r, 1);
        r += __shfl_xor_sync(FULL, r, 2);
        r += __shfl_xor_sync(FULL, r, 4);
        if (lane == 0) atomicAdd(&out[b], r);
    }
}

// ---------------- launch ------------------------------------------------------
extern "C" void kernel_launch(void* const* d_in, const int* in_sizes, int n_in,
                              void* d_out, int out_size) {
    const float* x       = (const float*)d_in[0];   // (32,1024,1)
    const float* weights = (const float*)d_in[1];   // (3,8)
    const float* dw      = (const float*)d_in[2];   // (1022,1)
    const float* db      = (const float*)d_in[3];   // (1,)
    float* out = (float*)d_out;                     // (32,1)

    gridsim_kernel<<<81, 32>>>(weights, db, out);
    dim3 g((1022 + CH - 1) / CH, 32);               // (8, 32)
    fused_kernel<<<g, 256>>>(x, dw, out);
}